// round 8
// baseline (speedup 1.0000x reference)
#include <cuda_runtime.h>
#include <cstdint>

// Problem constants
#define B_   32
#define C_   256
#define H_   58
#define W_   58
#define OC_  256
#define KH_  3
#define KW_  3
#define HO_  56
#define WO_  56
#define HW_  (H_*W_)            // 3364
#define NWORDS 8                // 256 channels / 32 bits
#define CN_  2304               // C*KH*KW
#define NINPUT 861184.0f        // C*H*W (alpha normalizer)

// Scratch (device globals; no allocations allowed)
__device__ unsigned g_xpack[B_ * HW_ * NWORDS];        // [b][y][x][w]  3.44 MB
__device__ unsigned g_wpack[OC_ * KH_ * KW_ * NWORDS]; // [o][k][w]     73.7 KB
__device__ float    g_alpha[OC_];

// Forced single-LOP3 3-input ops
template <int LUT>
__device__ __forceinline__ unsigned lop3(unsigned a, unsigned b, unsigned c) {
    unsigned r;
    asm("lop3.b32 %0, %1, %2, %3, %4;" : "=r"(r) : "r"(a), "r"(b), "r"(c), "n"(LUT));
    return r;
}
#define XOR3(a,b,c)  lop3<0x96>(a,b,c)                 // a^b^c
#define MAJ3(a,b,c)  lop3<0xE8>(a,b,c)                 // majority
#define MAJU(x,y,u)  lop3<0xD4>(x,y,u)                 // (x&y)|((x^y)&~u)

// ---------------------------------------------------------------------------
// Pass 1: pack binary activations over the channel dimension. (HBM-roofline)
// ---------------------------------------------------------------------------
__global__ void pack_x_kernel(const float* __restrict__ x) {
    int bw = blockIdx.x;
    int b  = bw >> 3;
    int w  = bw & 7;
    int pos = blockIdx.y * blockDim.x + threadIdx.x;
    if (pos >= HW_) return;

    const float* xp = x + ((size_t)(b * C_ + w * 32) * HW_) + pos;
    unsigned bits = 0;
#pragma unroll
    for (int c = 0; c < 32; c++) {
        float v = __ldg(xp + (size_t)c * HW_);
        bits |= (v > 0.5f ? 1u : 0u) << c;
    }
    g_xpack[((size_t)b * HW_ + pos) * NWORDS + w] = bits;
}

// ---------------------------------------------------------------------------
// Pass 2: pack binarized weights (ballot) + alpha per filter.
// ---------------------------------------------------------------------------
__global__ void pack_w_kernel(const float* __restrict__ wgt) {
    int o = blockIdx.x;
    int c = threadIdx.x;
    int lane = c & 31;
    int wrp  = c >> 5;

    const float* wp = wgt + (size_t)(o * C_ + c) * (KH_ * KW_);
    float asum = 0.f;
#pragma unroll
    for (int k = 0; k < KH_ * KW_; k++) {
        float v = wp[k];
        asum += fabsf(v);
        unsigned word = __ballot_sync(0xffffffffu, v >= 0.f);
        if (lane == 0) g_wpack[(o * 9 + k) * NWORDS + wrp] = word;
    }

    __shared__ float red[256];
    red[c] = asum;
    __syncthreads();
#pragma unroll
    for (int s = 128; s > 0; s >>= 1) {
        if (c < s) red[c] += red[c + s];
        __syncthreads();
    }
    if (c == 0) g_alpha[o] = red[0] / NINPUT;
}

// ---------------------------------------------------------------------------
// Pass 3: XNOR conv, two-level CSA + word-split occupancy.
// 512 threads: o = tid&255 (output channel), half = tid>>8 (channel words
// 4*half..4*half+3). Each thread-pair shares an output; partials packed as
// P0|P1<<16 into smem, combined once at the end.
// Math per (word,kh,output): u = s3^wx3; v = MAJU(p^w0, p'^w1, u);
// level-2 over kh: XOR3/MAJ3 -> 4 POPC per word with weights (1,2,2,4).
// grid = B_*HO_, block = 512.
// ---------------------------------------------------------------------------
#define SX_WORDS  (3 * W_  * NWORDS)    // 1392
#define S3_WORDS  (3 * WO_ * NWORDS)    // 1344
#define BUF_WORDS (2 * 256 * 28)        // 14336
#define SMEM_BYTES ((SX_WORDS + S3_WORDS + BUF_WORDS) * 4)  // 68288

__global__ void __launch_bounds__(512, 1)
xnor_conv_kernel(float* __restrict__ out) {
    extern __shared__ __align__(16) unsigned sm[];
    unsigned* sx  = sm;
    unsigned* s3  = sm + SX_WORDS;
    unsigned* buf = sm + SX_WORDS + S3_WORDS;

    int by = blockIdx.x;
    int b  = by / HO_;
    int y  = by % HO_;
    int t    = threadIdx.x;
    int o    = t & 255;
    int half = t >> 8;

    // load 3 packed rows
    const int ROW4 = W_ * NWORDS / 4; // 116 uint4 per row
    for (int i = t; i < 3 * ROW4; i += 512) {
        int kh = i / ROW4;
        int r  = i - kh * ROW4;
        const uint4* src = (const uint4*)(g_xpack + ((size_t)(b * H_ + y + kh) * W_) * NWORDS);
        ((uint4*)sx)[kh * ROW4 + r] = src[r];
    }

    // per-thread weights for this thread's 4 words: w0, w1, wx3 laid out [kh*4+j]
    unsigned w0[12], w1[12], wx3[12];
    {
        const uint4* wp4 = (const uint4*)(g_wpack + o * 72);
#pragma unroll
        for (int kh = 0; kh < 3; kh++) {
            uint4 a = wp4[(kh * 3 + 0) * 2 + half];
            uint4 bq = wp4[(kh * 3 + 1) * 2 + half];
            uint4 c = wp4[(kh * 3 + 2) * 2 + half];
            ((uint4*)w0)[kh] = a;
            ((uint4*)w1)[kh] = bq;
            wx3[kh * 4 + 0] = a.x ^ bq.x ^ c.x;
            wx3[kh * 4 + 1] = a.y ^ bq.y ^ c.y;
            wx3[kh * 4 + 2] = a.z ^ bq.z ^ c.z;
            wx3[kh * 4 + 3] = a.w ^ bq.w ^ c.w;
        }
    }
    float alpha = g_alpha[o];
    __syncthreads();

    // s3[kh][c][w] = sx[kh][c] ^ sx[kh][c+1] ^ sx[kh][c+2]
    for (int i = t; i < S3_WORDS; i += 512) {
        int kh = i / (WO_ * NWORDS);
        int r  = i - kh * (WO_ * NWORDS);
        int base = kh * (W_ * NWORDS) + r;
        s3[i] = XOR3(sx[base], sx[base + NWORDS], sx[base + 2 * NWORDS]);
    }
    __syncthreads();

    unsigned* mybuf = buf + half * (256 * 28) + o * 28;

#pragma unroll 1
    for (int x0 = 0; x0 < WO_; x0 += 2) {
        unsigned u[3][2][4], v[3][2][4];     // [kh][xi][j]
#pragma unroll
        for (int kh = 0; kh < 3; kh++) {
            const unsigned* rp = &sx[(kh * W_ + x0) * NWORDS + half * 4];
            uint4 q0 = *(const uint4*)(rp);
            uint4 q1 = *(const uint4*)(rp + NWORDS);
            uint4 q2 = *(const uint4*)(rp + 2 * NWORDS);
            const unsigned* rs = &s3[(kh * WO_ + x0) * NWORDS + half * 4];
            uint4 t0 = *(const uint4*)(rs);
            uint4 t1 = *(const uint4*)(rs + NWORDS);
            unsigned p0[4] = {q0.x, q0.y, q0.z, q0.w};
            unsigned p1[4] = {q1.x, q1.y, q1.z, q1.w};
            unsigned p2[4] = {q2.x, q2.y, q2.z, q2.w};
            unsigned s0[4] = {t0.x, t0.y, t0.z, t0.w};
            unsigned s1[4] = {t1.x, t1.y, t1.z, t1.w};
#pragma unroll
            for (int j = 0; j < 4; j++) {
                int wi = kh * 4 + j;
                unsigned W0 = w0[wi], W1 = w1[wi], WX = wx3[wi];
                unsigned u0 = s0[j] ^ WX;
                unsigned u1 = s1[j] ^ WX;
                u[kh][0][j] = u0;
                u[kh][1][j] = u1;
                v[kh][0][j] = MAJU(p0[j] ^ W0, p1[j] ^ W1, u0);
                v[kh][1][j] = MAJU(p1[j] ^ W0, p2[j] ^ W1, u1);
            }
        }
        int P0 = 0, P1 = 0;
#pragma unroll
        for (int xi = 0; xi < 2; xi++) {
#pragma unroll
            for (int j = 0; j < 4; j++) {
                unsigned su = XOR3(u[0][xi][j], u[1][xi][j], u[2][xi][j]);
                unsigned cu = MAJ3(u[0][xi][j], u[1][xi][j], u[2][xi][j]);
                unsigned sv = XOR3(v[0][xi][j], v[1][xi][j], v[2][xi][j]);
                unsigned cv = MAJ3(v[0][xi][j], v[1][xi][j], v[2][xi][j]);
                int tt = __popc(su) + ((__popc(cu) + __popc(sv)) << 1)
                       + (__popc(cv) << 2);
                if (xi == 0) P0 += tt; else P1 += tt;
            }
        }
        mybuf[x0 >> 1] = (unsigned)P0 | ((unsigned)P1 << 16);
    }
    __syncthreads();

    // Combine halves: each thread handles 14 x-pairs of its o.
    const unsigned* b0 = buf + o * 28;
    const unsigned* b1 = buf + 256 * 28 + o * 28;
    float* outp = out + ((size_t)(b * OC_ + o) * HO_ + y) * WO_;
    int k0 = half * 14;
#pragma unroll
    for (int k = 0; k < 14; k++) {
        unsigned pp = b0[k0 + k] + b1[k0 + k];   // fields sum w/o carry (<=2304)
        int lo = pp & 0xFFFF;
        int hi = pp >> 16;
        float2 r;
        r.x = alpha * (float)(CN_ - 2 * lo);
        r.y = alpha * (float)(CN_ - 2 * hi);
        *(float2*)(outp + 2 * (k0 + k)) = r;
    }
}

// ---------------------------------------------------------------------------
extern "C" void kernel_launch(void* const* d_in, const int* in_sizes, int n_in,
                              void* d_out, int out_size) {
    const float* x   = (const float*)d_in[0];
    const float* wgt = (const float*)d_in[1];
    float* out = (float*)d_out;

    cudaFuncSetAttribute(xnor_conv_kernel,
                         cudaFuncAttributeMaxDynamicSharedMemorySize, SMEM_BYTES);

    dim3 g1(B_ * NWORDS, (HW_ + 255) / 256);
    pack_x_kernel<<<g1, 256>>>(x);
    pack_w_kernel<<<OC_, 256>>>(wgt);
    xnor_conv_kernel<<<B_ * HO_, 512, SMEM_BYTES>>>(out);
}

// round 9
// speedup vs baseline: 1.2582x; 1.2582x over previous
#include <cuda_runtime.h>
#include <cstdint>

// Problem constants
#define B_   32
#define C_   256
#define H_   58
#define W_   58
#define OC_  256
#define KH_  3
#define KW_  3
#define HO_  56
#define WO_  56
#define HW_  (H_*W_)            // 3364
#define NWORDS 8                // 256 channels / 32 bits
#define CN_  2304               // C*KH*KW
#define NINPUT 861184.0f        // C*H*W (alpha normalizer)

// Scratch (device globals; no allocations allowed)
__device__ unsigned g_xpack[B_ * HW_ * NWORDS];        // [b][y][x][w]  3.44 MB
__device__ unsigned g_wpack[OC_ * KH_ * KW_ * NWORDS]; // [o][k][w]     73.7 KB
__device__ float    g_alpha[OC_];

// Forced single-LOP3 3-input ops
template <int LUT>
__device__ __forceinline__ unsigned lop3(unsigned a, unsigned b, unsigned c) {
    unsigned r;
    asm("lop3.b32 %0, %1, %2, %3, %4;" : "=r"(r) : "r"(a), "r"(b), "r"(c), "n"(LUT));
    return r;
}
#define XOR3(a,b,c)  lop3<0x96>(a,b,c)                 // a^b^c
#define MAJ3(a,b,c)  lop3<0xE8>(a,b,c)                 // majority
#define MAJU(x,y,u)  lop3<0xD4>(x,y,u)                 // (x&y)|((x^y)&~u)

// ---------------------------------------------------------------------------
// Pass 1: pack binary activations over the channel dimension. (HBM-roofline)
// ---------------------------------------------------------------------------
__global__ void pack_x_kernel(const float* __restrict__ x) {
    int bw = blockIdx.x;
    int b  = bw >> 3;
    int w  = bw & 7;
    int pos = blockIdx.y * blockDim.x + threadIdx.x;
    if (pos >= HW_) return;

    const float* xp = x + ((size_t)(b * C_ + w * 32) * HW_) + pos;
    unsigned bits = 0;
#pragma unroll
    for (int c = 0; c < 32; c++) {
        float v = __ldg(xp + (size_t)c * HW_);
        bits |= (v > 0.5f ? 1u : 0u) << c;
    }
    g_xpack[((size_t)b * HW_ + pos) * NWORDS + w] = bits;
}

// ---------------------------------------------------------------------------
// Pass 2: pack binarized weights (ballot) + alpha per filter.
// ---------------------------------------------------------------------------
__global__ void pack_w_kernel(const float* __restrict__ wgt) {
    int o = blockIdx.x;
    int c = threadIdx.x;
    int lane = c & 31;
    int wrp  = c >> 5;

    const float* wp = wgt + (size_t)(o * C_ + c) * (KH_ * KW_);
    float asum = 0.f;
#pragma unroll
    for (int k = 0; k < KH_ * KW_; k++) {
        float v = wp[k];
        asum += fabsf(v);
        unsigned word = __ballot_sync(0xffffffffu, v >= 0.f);
        if (lane == 0) g_wpack[(o * 9 + k) * NWORDS + wrp] = word;
    }

    __shared__ float red[256];
    red[c] = asum;
    __syncthreads();
#pragma unroll
    for (int s = 128; s > 0; s >>= 1) {
        if (c < s) red[c] += red[c + s];
        __syncthreads();
    }
    if (c == 0) g_alpha[o] = red[0] / NINPUT;
}

// ---------------------------------------------------------------------------
// Pass 3: XNOR conv, two-level CSA (R7 math) with:
//  - 128-thread blocks, 3 CTAs/SM (grid split over o-halves): 3 warps/SMSP
//  - deferred 1/2/2/4 weighting: 4 plain popc accumulators per output,
//    weights applied once at the end (removes per-word shifts/combine)
// grid = (B_*HO_, 2), block = 128 (thread = output channel within half).
// ---------------------------------------------------------------------------
__global__ void __launch_bounds__(128, 3)
xnor_conv_kernel(float* __restrict__ out) {
    int by = blockIdx.x;
    int b  = by / HO_;
    int y  = by % HO_;
    int o  = blockIdx.y * 128 + threadIdx.x;
    int t  = threadIdx.x;

    __shared__ __align__(16) unsigned sx[3 * W_  * NWORDS];  // 5568 B
    __shared__ __align__(16) unsigned s3[3 * WO_ * NWORDS];  // 5376 B

    // load 3 packed rows
    const int ROW4 = W_ * NWORDS / 4; // 116 uint4 per row
    for (int i = t; i < 3 * ROW4; i += 128) {
        int kh = i / ROW4;
        int r  = i - kh * ROW4;
        const uint4* src = (const uint4*)(g_xpack + ((size_t)(b * H_ + y + kh) * W_) * NWORDS);
        ((uint4*)sx)[kh * ROW4 + r] = src[r];
    }

    // per-thread weights: w0, w1 (kw taps 0,1) and wx3 = w0^w1^w2, [kh*8+w]
    unsigned w0[24], w1[24], wx3[24];
    {
        const uint4* wp4 = (const uint4*)(g_wpack + (size_t)o * 72);
#pragma unroll
        for (int kh = 0; kh < 3; kh++) {
            uint4 a0 = wp4[(kh * 3 + 0) * 2], a1 = wp4[(kh * 3 + 0) * 2 + 1];
            uint4 b0 = wp4[(kh * 3 + 1) * 2], b1 = wp4[(kh * 3 + 1) * 2 + 1];
            uint4 c0 = wp4[(kh * 3 + 2) * 2], c1 = wp4[(kh * 3 + 2) * 2 + 1];
            ((uint4*)w0)[kh * 2] = a0; ((uint4*)w0)[kh * 2 + 1] = a1;
            ((uint4*)w1)[kh * 2] = b0; ((uint4*)w1)[kh * 2 + 1] = b1;
            wx3[kh * 8 + 0] = a0.x ^ b0.x ^ c0.x;
            wx3[kh * 8 + 1] = a0.y ^ b0.y ^ c0.y;
            wx3[kh * 8 + 2] = a0.z ^ b0.z ^ c0.z;
            wx3[kh * 8 + 3] = a0.w ^ b0.w ^ c0.w;
            wx3[kh * 8 + 4] = a1.x ^ b1.x ^ c1.x;
            wx3[kh * 8 + 5] = a1.y ^ b1.y ^ c1.y;
            wx3[kh * 8 + 6] = a1.z ^ b1.z ^ c1.z;
            wx3[kh * 8 + 7] = a1.w ^ b1.w ^ c1.w;
        }
    }
    float a = g_alpha[o];
    __syncthreads();

    // s3[kh][c][w] = sx[kh][c] ^ sx[kh][c+1] ^ sx[kh][c+2]
    for (int i = t; i < 3 * WO_ * NWORDS; i += 128) {
        int kh = i / (WO_ * NWORDS);
        int r  = i - kh * (WO_ * NWORDS);
        int base = kh * (W_ * NWORDS) + r;
        s3[i] = XOR3(sx[base], sx[base + NWORDS], sx[base + 2 * NWORDS]);
    }
    __syncthreads();

    float* outp = out + ((size_t)(b * OC_ + o) * HO_ + y) * WO_;

#pragma unroll 1
    for (int x0 = 0; x0 < WO_; x0 += 2) {
        int Su0 = 0, Cu0 = 0, Sv0 = 0, Cv0 = 0;
        int Su1 = 0, Cu1 = 0, Sv1 = 0, Cv1 = 0;
#pragma unroll
        for (int half = 0; half < 2; half++) {
            unsigned u[3][2][4], v[3][2][4];     // [kh][xi][j]
#pragma unroll
            for (int kh = 0; kh < 3; kh++) {
                const unsigned* rp = &sx[(kh * W_ + x0) * NWORDS + half * 4];
                uint4 q0 = *(const uint4*)(rp);
                uint4 q1 = *(const uint4*)(rp + NWORDS);
                uint4 q2 = *(const uint4*)(rp + 2 * NWORDS);
                const unsigned* rs = &s3[(kh * WO_ + x0) * NWORDS + half * 4];
                uint4 t0 = *(const uint4*)(rs);
                uint4 t1 = *(const uint4*)(rs + NWORDS);
                unsigned p0[4] = {q0.x, q0.y, q0.z, q0.w};
                unsigned p1[4] = {q1.x, q1.y, q1.z, q1.w};
                unsigned p2[4] = {q2.x, q2.y, q2.z, q2.w};
                unsigned s0[4] = {t0.x, t0.y, t0.z, t0.w};
                unsigned s1[4] = {t1.x, t1.y, t1.z, t1.w};
#pragma unroll
                for (int j = 0; j < 4; j++) {
                    int wi = kh * 8 + half * 4 + j;
                    unsigned W0 = w0[wi], W1 = w1[wi], WX = wx3[wi];
                    unsigned u0 = s0[j] ^ WX;
                    unsigned u1 = s1[j] ^ WX;
                    u[kh][0][j] = u0;
                    u[kh][1][j] = u1;
                    v[kh][0][j] = MAJU(p0[j] ^ W0, p1[j] ^ W1, u0);
                    v[kh][1][j] = MAJU(p1[j] ^ W0, p2[j] ^ W1, u1);
                }
            }
#pragma unroll
            for (int j = 0; j < 4; j++) {
                Su0 += __popc(XOR3(u[0][0][j], u[1][0][j], u[2][0][j]));
                Cu0 += __popc(MAJ3(u[0][0][j], u[1][0][j], u[2][0][j]));
                Sv0 += __popc(XOR3(v[0][0][j], v[1][0][j], v[2][0][j]));
                Cv0 += __popc(MAJ3(v[0][0][j], v[1][0][j], v[2][0][j]));
                Su1 += __popc(XOR3(u[0][1][j], u[1][1][j], u[2][1][j]));
                Cu1 += __popc(MAJ3(u[0][1][j], u[1][1][j], u[2][1][j]));
                Sv1 += __popc(XOR3(v[0][1][j], v[1][1][j], v[2][1][j]));
                Cv1 += __popc(MAJ3(v[0][1][j], v[1][1][j], v[2][1][j]));
            }
        }
        int P0 = Su0 + ((Cu0 + Sv0) << 1) + (Cv0 << 2);
        int P1 = Su1 + ((Cu1 + Sv1) << 1) + (Cv1 << 2);
        float2 r;
        r.x = a * (float)(CN_ - 2 * P0);
        r.y = a * (float)(CN_ - 2 * P1);
        *(float2*)(outp + x0) = r;
    }
}

// ---------------------------------------------------------------------------
extern "C" void kernel_launch(void* const* d_in, const int* in_sizes, int n_in,
                              void* d_out, int out_size) {
    const float* x   = (const float*)d_in[0];
    const float* wgt = (const float*)d_in[1];
    float* out = (float*)d_out;

    dim3 g1(B_ * NWORDS, (HW_ + 255) / 256);
    pack_x_kernel<<<g1, 256>>>(x);
    pack_w_kernel<<<OC_, 256>>>(wgt);
    dim3 g3(B_ * HO_, 2);
    xnor_conv_kernel<<<g3, 128>>>(out);
}

// round 10
// speedup vs baseline: 1.2892x; 1.0247x over previous
#include <cuda_runtime.h>
#include <cstdint>

// Problem constants
#define B_   32
#define C_   256
#define H_   58
#define W_   58
#define OC_  256
#define KH_  3
#define KW_  3
#define HO_  56
#define WO_  56
#define HW_  (H_*W_)            // 3364
#define NWORDS 8                // 256 channels / 32 bits
#define CN_  2304               // C*KH*KW
#define NINPUT 861184.0f        // C*H*W (alpha normalizer)

// Scratch (device globals; no allocations allowed)
__device__ unsigned g_xpack[B_ * HW_ * NWORDS];        // [b][y][x][w]  3.44 MB
__device__ unsigned g_wpack[OC_ * KH_ * KW_ * NWORDS]; // [o][k][w]     73.7 KB
__device__ float    g_alpha[OC_];

// Forced single-LOP3 3-input ops
template <int LUT>
__device__ __forceinline__ unsigned lop3(unsigned a, unsigned b, unsigned c) {
    unsigned r;
    asm("lop3.b32 %0, %1, %2, %3, %4;" : "=r"(r) : "r"(a), "r"(b), "r"(c), "n"(LUT));
    return r;
}
#define XOR3(a,b,c)  lop3<0x96>(a,b,c)                 // a^b^c
#define MAJ3(a,b,c)  lop3<0xE8>(a,b,c)                 // majority
#define MAJU(x,y,u)  lop3<0xD4>(x,y,u)                 // (x&y)|((x^y)&~u)

// ---------------------------------------------------------------------------
// Fused pack kernel. 1D grid of 2048 blocks x 256 threads:
//   blocks [0,1792): pack activations, 2 positions per thread, high MLP
//   blocks [1792,2048): pack weights (ballot) + alpha
// ---------------------------------------------------------------------------
#define XBLOCKS (B_ * NWORDS * 7)   // 32 b x 8 w x 7 pos-chunks = 1792

__global__ void __launch_bounds__(256) pack_kernel(const float* __restrict__ x,
                                                   const float* __restrict__ wgt) {
    int blk = blockIdx.x;
    if (blk < XBLOCKS) {
        // ---- activation packing ----
        int b    = blk / 56;
        int rem  = blk % 56;
        int w    = rem / 7;
        int pblk = rem % 7;
        int pos0 = pblk * 512 + threadIdx.x;   // positions pos0, pos0+256

        const float* xp = x + ((size_t)(b * C_ + w * 32) * HW_);
        float v0[32], v1[32];
        bool ok0 = pos0 < HW_;
        bool ok1 = pos0 + 256 < HW_;
#pragma unroll
        for (int c = 0; c < 32; c++) {
            size_t off = (size_t)c * HW_;
            v0[c] = ok0 ? __ldg(xp + off + pos0)       : 0.f;
            v1[c] = ok1 ? __ldg(xp + off + pos0 + 256) : 0.f;
        }
        unsigned bits0 = 0, bits1 = 0;
#pragma unroll
        for (int c = 0; c < 32; c++) {
            bits0 |= (v0[c] > 0.5f ? 1u : 0u) << c;
            bits1 |= (v1[c] > 0.5f ? 1u : 0u) << c;
        }
        if (ok0) g_xpack[((size_t)b * HW_ + pos0) * NWORDS + w] = bits0;
        if (ok1) g_xpack[((size_t)b * HW_ + pos0 + 256) * NWORDS + w] = bits1;
    } else {
        // ---- weight packing + alpha ----
        int o = blk - XBLOCKS;
        int c = threadIdx.x;
        int lane = c & 31;
        int wrp  = c >> 5;

        const float* wp = wgt + (size_t)(o * C_ + c) * (KH_ * KW_);
        float asum = 0.f;
#pragma unroll
        for (int k = 0; k < KH_ * KW_; k++) {
            float v = wp[k];
            asum += fabsf(v);
            unsigned word = __ballot_sync(0xffffffffu, v >= 0.f);
            if (lane == 0) g_wpack[(o * 9 + k) * NWORDS + wrp] = word;
        }

        __shared__ float red[256];
        red[c] = asum;
        __syncthreads();
#pragma unroll
        for (int s = 128; s > 0; s >>= 1) {
            if (c < s) red[c] += red[c + s];
            __syncthreads();
        }
        if (c == 0) g_alpha[o] = red[0] / NINPUT;
    }
}

// ---------------------------------------------------------------------------
// Conv: two-level CSA XNOR conv (R9 structure), 3 CTAs/SM,
// fma-pipe epilogue, x0 loop unrolled 2x.
// grid = (B_*HO_, 2), block = 128 (thread = output channel within half).
// ---------------------------------------------------------------------------
__global__ void __launch_bounds__(128, 3)
xnor_conv_kernel(float* __restrict__ out) {
    int by = blockIdx.x;
    int b  = by / HO_;
    int y  = by % HO_;
    int o  = blockIdx.y * 128 + threadIdx.x;
    int t  = threadIdx.x;

    __shared__ __align__(16) unsigned sx[3 * W_  * NWORDS];  // 5568 B
    __shared__ __align__(16) unsigned s3[3 * WO_ * NWORDS];  // 5376 B

    // load 3 packed rows
    const int ROW4 = W_ * NWORDS / 4; // 116 uint4 per row
    for (int i = t; i < 3 * ROW4; i += 128) {
        int kh = i / ROW4;
        int r  = i - kh * ROW4;
        const uint4* src = (const uint4*)(g_xpack + ((size_t)(b * H_ + y + kh) * W_) * NWORDS);
        ((uint4*)sx)[kh * ROW4 + r] = src[r];
    }

    // per-thread weights: w0, w1 (kw taps 0,1) and wx3 = w0^w1^w2, [kh*8+w]
    unsigned w0[24], w1[24], wx3[24];
    {
        const uint4* wp4 = (const uint4*)(g_wpack + (size_t)o * 72);
#pragma unroll
        for (int kh = 0; kh < 3; kh++) {
            uint4 a0 = wp4[(kh * 3 + 0) * 2], a1 = wp4[(kh * 3 + 0) * 2 + 1];
            uint4 b0 = wp4[(kh * 3 + 1) * 2], b1 = wp4[(kh * 3 + 1) * 2 + 1];
            uint4 c0 = wp4[(kh * 3 + 2) * 2], c1 = wp4[(kh * 3 + 2) * 2 + 1];
            ((uint4*)w0)[kh * 2] = a0; ((uint4*)w0)[kh * 2 + 1] = a1;
            ((uint4*)w1)[kh * 2] = b0; ((uint4*)w1)[kh * 2 + 1] = b1;
            wx3[kh * 8 + 0] = a0.x ^ b0.x ^ c0.x;
            wx3[kh * 8 + 1] = a0.y ^ b0.y ^ c0.y;
            wx3[kh * 8 + 2] = a0.z ^ b0.z ^ c0.z;
            wx3[kh * 8 + 3] = a0.w ^ b0.w ^ c0.w;
            wx3[kh * 8 + 4] = a1.x ^ b1.x ^ c1.x;
            wx3[kh * 8 + 5] = a1.y ^ b1.y ^ c1.y;
            wx3[kh * 8 + 6] = a1.z ^ b1.z ^ c1.z;
            wx3[kh * 8 + 7] = a1.w ^ b1.w ^ c1.w;
        }
    }
    float a = g_alpha[o];
    float base = a * (float)CN_;     // out = base + na * P
    float na   = -2.0f * a;
    __syncthreads();

    // s3[kh][c][w] = sx[kh][c] ^ sx[kh][c+1] ^ sx[kh][c+2]
    for (int i = t; i < 3 * WO_ * NWORDS; i += 128) {
        int kh = i / (WO_ * NWORDS);
        int r  = i - kh * (WO_ * NWORDS);
        int bidx = kh * (W_ * NWORDS) + r;
        s3[i] = XOR3(sx[bidx], sx[bidx + NWORDS], sx[bidx + 2 * NWORDS]);
    }
    __syncthreads();

    float* outp = out + ((size_t)(b * OC_ + o) * HO_ + y) * WO_;

#pragma unroll 2
    for (int x0 = 0; x0 < WO_; x0 += 2) {
        int Su0 = 0, Cu0 = 0, Sv0 = 0, Cv0 = 0;
        int Su1 = 0, Cu1 = 0, Sv1 = 0, Cv1 = 0;
#pragma unroll
        for (int half = 0; half < 2; half++) {
            unsigned u[3][2][4], v[3][2][4];     // [kh][xi][j]
#pragma unroll
            for (int kh = 0; kh < 3; kh++) {
                const unsigned* rp = &sx[(kh * W_ + x0) * NWORDS + half * 4];
                uint4 q0 = *(const uint4*)(rp);
                uint4 q1 = *(const uint4*)(rp + NWORDS);
                uint4 q2 = *(const uint4*)(rp + 2 * NWORDS);
                const unsigned* rs = &s3[(kh * WO_ + x0) * NWORDS + half * 4];
                uint4 t0 = *(const uint4*)(rs);
                uint4 t1 = *(const uint4*)(rs + NWORDS);
                unsigned p0[4] = {q0.x, q0.y, q0.z, q0.w};
                unsigned p1[4] = {q1.x, q1.y, q1.z, q1.w};
                unsigned p2[4] = {q2.x, q2.y, q2.z, q2.w};
                unsigned s0[4] = {t0.x, t0.y, t0.z, t0.w};
                unsigned s1[4] = {t1.x, t1.y, t1.z, t1.w};
#pragma unroll
                for (int j = 0; j < 4; j++) {
                    int wi = kh * 8 + half * 4 + j;
                    unsigned W0 = w0[wi], W1 = w1[wi], WX = wx3[wi];
                    unsigned u0 = s0[j] ^ WX;
                    unsigned u1 = s1[j] ^ WX;
                    u[kh][0][j] = u0;
                    u[kh][1][j] = u1;
                    v[kh][0][j] = MAJU(p0[j] ^ W0, p1[j] ^ W1, u0);
                    v[kh][1][j] = MAJU(p1[j] ^ W0, p2[j] ^ W1, u1);
                }
            }
#pragma unroll
            for (int j = 0; j < 4; j++) {
                Su0 += __popc(XOR3(u[0][0][j], u[1][0][j], u[2][0][j]));
                Cu0 += __popc(MAJ3(u[0][0][j], u[1][0][j], u[2][0][j]));
                Sv0 += __popc(XOR3(v[0][0][j], v[1][0][j], v[2][0][j]));
                Cv0 += __popc(MAJ3(v[0][0][j], v[1][0][j], v[2][0][j]));
                Su1 += __popc(XOR3(u[0][1][j], u[1][1][j], u[2][1][j]));
                Cu1 += __popc(MAJ3(u[0][1][j], u[1][1][j], u[2][1][j]));
                Sv1 += __popc(XOR3(v[0][1][j], v[1][1][j], v[2][1][j]));
                Cv1 += __popc(MAJ3(v[0][1][j], v[1][1][j], v[2][1][j]));
            }
        }
        int P0 = Su0 + ((Cu0 + Sv0) << 1) + (Cv0 << 2);
        int P1 = Su1 + ((Cu1 + Sv1) << 1) + (Cv1 << 2);
        float2 r;
        r.x = fmaf(na, (float)P0, base);
        r.y = fmaf(na, (float)P1, base);
        *(float2*)(outp + x0) = r;
    }
}

// ---------------------------------------------------------------------------
extern "C" void kernel_launch(void* const* d_in, const int* in_sizes, int n_in,
                              void* d_out, int out_size) {
    const float* x   = (const float*)d_in[0];
    const float* wgt = (const float*)d_in[1];
    float* out = (float*)d_out;

    pack_kernel<<<XBLOCKS + OC_, 256>>>(x, wgt);
    dim3 g3(B_ * HO_, 2);
    xnor_conv_kernel<<<g3, 128>>>(out);
}